// round 14
// baseline (speedup 1.0000x reference)
#include <cuda_runtime.h>
#include <math.h>

#define D 4096
#define NCLS 100
#define KSUP 5
#define QPER 75
#define ROWSPC 80
#define NQ 7500
#define EPSC 1e-8f
#define GAPT_RAW 0.008f
#define MAXC 8
#define MAXA 1024

// ---------------- scratch ----------------
__device__ float g_proto[NCLS * D];
__device__ float g_pn[NCLS * D];        // exact fp32 normalized protos (refine)
__device__ float g_pnh[NCLS * D];       // RNA tf32 pn (gemm B)
__device__ float g_anh[NCLS * D];       // RNA tf32 adapted protos (gemm B)
__device__ float g_acc[NCLS * D];       // unnormalized adapted protos
__device__ float g_nrmp[NCLS * 2];      // per-half sumsq partials
__device__ float g_self[NCLS];
__device__ float g_qinv[NQ];
__device__ float g_win[NQ];
__device__ int   g_label[NQ];
__device__ int   g_cand[NQ * MAXC];
__device__ int   g_ncand[NQ];
__device__ int   g_work[NQ];
__device__ int   g_nwork;
__device__ float g_w[NCLS * MAXA];
__device__ int   g_joff[NCLS * MAXA];
__device__ int   g_cnt[NCLS];
__device__ float g_wself[NCLS];

__device__ __forceinline__ int qrow(int j) {
    return (j / QPER) * ROWSPC + KSUP + (j % QPER);
}

__device__ __forceinline__ float f2tff(float f) {
    unsigned u;
    asm("cvt.rna.tf32.f32 %0, %1;" : "=r"(u) : "f"(f));
    return __uint_as_float(u);
}

// ---------------- block reductions ----------------
__device__ __forceinline__ float blk_sum(float v, float* sred) {
    int lane = threadIdx.x & 31, w = threadIdx.x >> 5;
#pragma unroll
    for (int o = 16; o > 0; o >>= 1) v += __shfl_down_sync(0xffffffffu, v, o);
    __syncthreads();
    if (lane == 0) sred[w] = v;
    __syncthreads();
    if (w == 0) {
        v = (lane < ((int)blockDim.x >> 5)) ? sred[lane] : 0.f;
#pragma unroll
        for (int o = 16; o > 0; o >>= 1) v += __shfl_down_sync(0xffffffffu, v, o);
        if (lane == 0) sred[0] = v;
    }
    __syncthreads();
    return sred[0];
}

__device__ __forceinline__ float blk_max(float v, float* sred) {
    int lane = threadIdx.x & 31, w = threadIdx.x >> 5;
#pragma unroll
    for (int o = 16; o > 0; o >>= 1) v = fmaxf(v, __shfl_down_sync(0xffffffffu, v, o));
    __syncthreads();
    if (lane == 0) sred[w] = v;
    __syncthreads();
    if (w == 0) {
        v = (lane < ((int)blockDim.x >> 5)) ? sred[lane] : -INFINITY;
#pragma unroll
        for (int o = 16; o > 0; o >>= 1) v = fmaxf(v, __shfl_down_sync(0xffffffffu, v, o));
        if (lane == 0) sred[0] = v;
    }
    __syncthreads();
    return sred[0];
}

// ---------------- 1) prototypes ----------------
__global__ void __launch_bounds__(1024) proto_kernel(const float* __restrict__ x) {
    __shared__ float sred[32];
    int c = blockIdx.x;
    int i = threadIdx.x;
    if (c == 0 && i == 0) g_nwork = 0;
    const float4* sup = (const float4*)(x + (size_t)c * ROWSPC * D);
    const int DQ = D / 4;
    float4 v0 = sup[i];
    float4 v1 = sup[DQ + i];
    float4 v2 = sup[2 * DQ + i];
    float4 v3 = sup[3 * DQ + i];
    float4 v4 = sup[4 * DQ + i];
    float4 s;
    s.x = (v0.x + v1.x + v2.x + v3.x + v4.x) * 0.2f;
    s.y = (v0.y + v1.y + v2.y + v3.y + v4.y) * 0.2f;
    s.z = (v0.z + v1.z + v2.z + v3.z + v4.z) * 0.2f;
    s.w = (v0.w + v1.w + v2.w + v3.w + v4.w) * 0.2f;
    ((float4*)(g_proto + (size_t)c * D))[i] = s;
    float ss = s.x * s.x + s.y * s.y + s.z * s.z + s.w * s.w;
    float tot = blk_sum(ss, sred);
    float inv = 1.f / fmaxf(sqrtf(tot), EPSC);
    float4 p;
    p.x = s.x * inv; p.y = s.y * inv; p.z = s.z * inv; p.w = s.w * inv;
    ((float4*)(g_pn + (size_t)c * D))[i] = p;
    float4 ph;
    ph.x = f2tff(p.x); ph.y = f2tff(p.y); ph.z = f2tff(p.z); ph.w = f2tff(p.w);
    ((float4*)(g_pnh + (size_t)c * D))[i] = ph;
    float ss2 = p.x * p.x + p.y * p.y + p.z * p.z + p.w * p.w;
    float t2 = blk_sum(ss2, sred);
    if (i == 0) g_self[c] = t2;
}

// ---------------- 2)/6) tf32 mma GEMM: 5-stage ring, wait_group 3, ONE sync/iter ----------------
#define BM 32
#define BNROWS 104
#define BK 32
#define APAD 36
#define NSTG 5
#define NIT (D / BK)
#define PSTRIDE 106

#define CPA16(dst, src, sz) \
    asm volatile("cp.async.cg.shared.global [%0], [%1], 16, %2;\n" :: "r"(dst), "l"(src), "r"(sz))

__device__ __forceinline__ void mma_tf32(float c[4], const unsigned a[4], const unsigned b[2]) {
    asm volatile(
        "mma.sync.aligned.m16n8k8.row.col.f32.tf32.tf32.f32 "
        "{%0,%1,%2,%3}, {%4,%5,%6,%7}, {%8,%9}, {%0,%1,%2,%3};\n"
        : "+f"(c[0]), "+f"(c[1]), "+f"(c[2]), "+f"(c[3])
        : "r"(a[0]), "r"(a[1]), "r"(a[2]), "r"(a[3]), "r"(b[0]), "r"(b[1]));
}

template <int FIN>
__global__ void __launch_bounds__(128, 2) mma_gemm(const float* __restrict__ x,
                                                   const float* __restrict__ B,
                                                   const float* __restrict__ taop,
                                                   float* __restrict__ out) {
    extern __shared__ float sm[];
    __shared__ float sq[BM];
    constexpr int SA = BM * APAD;          // 1152
    constexpr int SB = BNROWS * APAD;      // 3744
    constexpr int SS = SA + SB;            // 4896 floats per stage

    const int tid = threadIdx.x;
    const int lane = tid & 31;
    const int warp = tid >> 5;             // == wN, 0..3 (warp 3 pruned)
    const int g = lane >> 2;
    const int t4 = lane & 3;
    const int j0 = blockIdx.x * BM;
    const int nfr = (warp == 3) ? 1 : 4;

    float C[2][4][4];
#pragma unroll
    for (int mt = 0; mt < 2; mt++)
#pragma unroll
        for (int nt = 0; nt < 4; nt++)
#pragma unroll
            for (int r = 0; r < 4; r++) C[mt][nt][r] = 0.f;

    float qq = 0.f;

    const unsigned smbase = (unsigned)__cvta_generic_to_shared(sm);

    auto load_tile = [&](int stg, int k0) {
        unsigned abase = smbase + stg * SS * 4;
#pragma unroll
        for (int i = 0; i < 2; i++) {
            int idx = tid + i * 128;
            int row = idx >> 3, seg = idx & 7;
            int j = j0 + row;
            const float* src = x + (size_t)qrow(j < NQ ? j : NQ - 1) * D + k0 + seg * 4;
            unsigned dst = abase + (row * APAD + seg * 4) * 4;
            CPA16(dst, src, (j < NQ) ? 16 : 0);
        }
        unsigned bbase = abase + SA * 4;
#pragma unroll
        for (int i = 0; i < 7; i++) {
            int idx = tid + i * 128;
            if (idx < BNROWS * 8) {
                int n = idx >> 3, seg = idx & 7;
                const float* src = B + (size_t)(n < NCLS ? n : NCLS - 1) * D + k0 + seg * 4;
                unsigned dst = bbase + (n * APAD + seg * 4) * 4;
                CPA16(dst, src, (n < NCLS) ? 16 : 0);
            }
        }
        asm volatile("cp.async.commit_group;\n");
    };

    // prologue: four stages in flight
    load_tile(0, 0);
    load_tile(1, BK);
    load_tile(2, 2 * BK);
    load_tile(3, 3 * BK);

    for (int it = 0; it < NIT; it++) {
        int rem = NIT - 1 - it;                // loads still outstanding after this iter's prefetch
        if (rem >= 3)      asm volatile("cp.async.wait_group 3;\n");
        else if (rem == 2) asm volatile("cp.async.wait_group 2;\n");
        else if (rem == 1) asm volatile("cp.async.wait_group 1;\n");
        else               asm volatile("cp.async.wait_group 0;\n");
        __syncthreads();
        // sole barrier per iter: readers of stage (it+4)%5 finished in iter it-1,
        // guaranteed complete by THIS barrier -> safe to overwrite below.
        if (it + 4 < NIT) load_tile((it + 4) % NSTG, (it + 4) * BK);

        const float* As = sm + (it % NSTG) * SS;
        const float* Bs = As + SA;

        if (!FIN) {
            const float* Ar = As + (tid >> 2) * APAD + (tid & 3) * 8;
#pragma unroll
            for (int i = 0; i < 8; i++) { float v = Ar[i]; qq += v * v; }
        }

#pragma unroll
        for (int step = 0; step < 4; step++) {
            const int k = step * 8 + t4;
            unsigned a[2][4];
#pragma unroll
            for (int mt = 0; mt < 2; mt++) {
                int r0 = mt * 16 + g;
                a[mt][0] = __float_as_uint(As[r0 * APAD + k]);
                a[mt][1] = __float_as_uint(As[(r0 + 8) * APAD + k]);
                a[mt][2] = __float_as_uint(As[r0 * APAD + k + 4]);
                a[mt][3] = __float_as_uint(As[(r0 + 8) * APAD + k + 4]);
            }
            unsigned b[4][2];
#pragma unroll
            for (int nt = 0; nt < 4; nt++) {
                if (nt >= nfr) continue;
                int n0 = warp * 32 + nt * 8 + g;
                b[nt][0] = __float_as_uint(Bs[n0 * APAD + k]);
                b[nt][1] = __float_as_uint(Bs[n0 * APAD + k + 4]);
            }
#pragma unroll
            for (int mt = 0; mt < 2; mt++)
#pragma unroll
                for (int nt = 0; nt < 4; nt++) {
                    if (nt >= nfr) continue;
                    mma_tf32(C[mt][nt], a[mt], b[nt]);
                }
        }
    }
    __syncthreads();

    if (!FIN) {
        qq += __shfl_down_sync(0xffffffffu, qq, 1);
        qq += __shfl_down_sync(0xffffffffu, qq, 2);
        if ((tid & 3) == 0) {
            int r = tid >> 2;
            int j = j0 + r;
            float qi = 1.f / fmaxf(sqrtf(qq), EPSC);
            sq[r] = qi;
            if (j < NQ) g_qinv[j] = qi;
        }

        float* pres = sm;
#pragma unroll
        for (int mt = 0; mt < 2; mt++) {
            int r0 = mt * 16 + g;
#pragma unroll
            for (int half = 0; half < 2; half++) {
                int row = r0 + half * 8;
#pragma unroll
                for (int nt = 0; nt < 4; nt++) {
                    if (nt >= nfr) continue;
                    int c = warp * 32 + nt * 8 + 2 * t4;
                    pres[row * PSTRIDE + c]     = C[mt][nt][half * 2 + 0];
                    pres[row * PSTRIDE + c + 1] = C[mt][nt][half * 2 + 1];
                }
            }
        }
        __syncthreads();

#pragma unroll
        for (int r = 0; r < 8; r++) {
            int row = warp * 8 + r;
            int j = j0 + row;
            if (j >= NQ) continue;
            float v[4];
            float m = -INFINITY;
            int bi = 0x7fffffff;
#pragma unroll
            for (int t = 0; t < 4; t++) {
                int c = lane + 32 * t;
                v[t] = (c < NCLS) ? pres[row * PSTRIDE + c] : -INFINITY;
                if (v[t] > m) { m = v[t]; bi = c; }
            }
#pragma unroll
            for (int o = 16; o > 0; o >>= 1) {
                float ov = __shfl_xor_sync(0xffffffffu, m, o);
                int oi = __shfl_xor_sync(0xffffffffu, bi, o);
                if (ov > m || (ov == m && oi < bi)) { m = ov; bi = oi; }
            }
            float thr = m - GAPT_RAW;
            unsigned lml = (1u << lane) - 1u;
            int base = 0;
#pragma unroll
            for (int t = 0; t < 4; t++) {
                int c = lane + 32 * t;
                bool pred = (c < NCLS) && (v[t] >= thr);
                unsigned mask = __ballot_sync(0xffffffffu, pred);
                if (pred) {
                    int pos = base + __popc(mask & lml);
                    if (pos < MAXC) g_cand[j * MAXC + pos] = c;
                }
                base += __popc(mask);
            }
            if (lane == 0) {
                int nc = min(base, MAXC);
                g_ncand[j] = nc;
                if (nc == 1) {
                    g_label[j] = bi;
                    g_win[j] = m * sq[row];
                } else {
                    int p = atomicAdd(&g_nwork, 1);
                    g_work[p] = j;
                }
            }
        }
    } else {
        const float taov = taop[0];
#pragma unroll
        for (int mt = 0; mt < 2; mt++) {
            int r0 = mt * 16 + g;
#pragma unroll
            for (int half = 0; half < 2; half++) {
                int j = j0 + r0 + half * 8;
                if (j >= NQ) continue;
                float s = g_qinv[j] * taov;
#pragma unroll
                for (int nt = 0; nt < 4; nt++) {
                    if (nt >= nfr) continue;
                    int c = warp * 32 + nt * 8 + 2 * t4;
                    if (c < NCLS)     out[j * NCLS + c]     = C[mt][nt][half * 2 + 0] * s;
                    if (c + 1 < NCLS) out[j * NCLS + c + 1] = C[mt][nt][half * 2 + 1] * s;
                }
            }
        }
    }
}

// ---------------- 3) exact refine: block per entry, warp per candidate ----------------
__global__ void __launch_bounds__(256) refine_kernel(const float* __restrict__ x) {
    __shared__ float sdot[MAXC];
    int nw = g_nwork;
    int w = threadIdx.x >> 5;
    int lane = threadIdx.x & 31;
    for (int t = blockIdx.x; t < nw; t += gridDim.x) {
        int j = g_work[t];
        int nc = g_ncand[j];
        const float4* q = (const float4*)(x + (size_t)qrow(j) * D);
        if (w < nc) {
            int cc = g_cand[j * MAXC + w];
            const float4* p = (const float4*)(g_pn + (size_t)cc * D);
            float d = 0.f;
#pragma unroll 4
            for (int i = lane; i < D / 4; i += 32) {
                float4 a = q[i], b = p[i];
                d += a.x * b.x + a.y * b.y + a.z * b.z + a.w * b.w;
            }
#pragma unroll
            for (int o = 16; o > 0; o >>= 1) d += __shfl_xor_sync(0xffffffffu, d, o);
            if (lane == 0) sdot[w] = d;
        }
        __syncthreads();
        if (threadIdx.x == 0) {
            float best = -INFINITY;
            int bi = 0x7fffffff;
            for (int i = 0; i < nc; i++) {
                float v = sdot[i];
                int c = g_cand[j * MAXC + i];
                if (v > best || (v == best && c < bi)) { best = v; bi = c; }
            }
            g_label[j] = bi;
            g_win[j] = best * g_qinv[j];
        }
        __syncthreads();
    }
}

// ---------------- 4) softmax weights per class (shfl-scan gather) ----------------
__global__ void __launch_bounds__(256) weights_kernel() {
    __shared__ int   s_off[MAXA];
    __shared__ float sred[32];
    __shared__ int   wtot[9];

    int c = blockIdx.x, tid = threadIdx.x;
    int lane = tid & 31, wrp = tid >> 5;

    const int chunk = (NQ + 255) / 256;     // 30
    int jlo = tid * chunk, jhi = min(NQ, jlo + chunk);
    int cnt = 0;
    for (int j = jlo; j < jhi; j++) cnt += (g_label[j] == c);
    int incl = cnt;
#pragma unroll
    for (int o = 1; o < 32; o <<= 1) {
        int v = __shfl_up_sync(0xffffffffu, incl, o);
        if (lane >= o) incl += v;
    }
    int excl = incl - cnt;
    if (lane == 31) wtot[wrp] = incl;
    __syncthreads();
    if (wrp == 0 && lane < 8) {
        int v = wtot[lane];
        int e = v;
#pragma unroll
        for (int o = 1; o < 8; o <<= 1) {
            int u = __shfl_up_sync(0xffu, e, o);
            if (lane >= o) e += u;
        }
        wtot[lane] = e - v;
        if (lane == 7) wtot[8] = e;
    }
    __syncthreads();
    int pos = wtot[wrp] + excl;
    for (int j = jlo; j < jhi; j++)
        if (g_label[j] == c) { if (pos < MAXA) s_off[pos] = j; pos++; }
    int total = min(wtot[8], MAXA);
    __syncthreads();

    float m = g_self[c];
    for (int t = tid; t < total; t += 256) m = fmaxf(m, g_win[s_off[t]]);
    m = blk_max(m, sred);

    float se = 0.f;
    float ebuf[(MAXA + 255) / 256];
    for (int t = tid, r = 0; t < total; t += 256, r++) {
        float e = expf(g_win[s_off[t]] - m);
        ebuf[r] = e;
        se += e;
    }
    float eself = expf(g_self[c] - m);
    float Z = blk_sum(se, sred) + eself;
    float invZ = 1.f / Z;
    for (int t = tid, r = 0; t < total; t += 256, r++) {
        g_w[c * MAXA + t] = ebuf[r] * invZ;
        g_joff[c * MAXA + t] = qrow(s_off[t]) * D;
    }
    if (tid == 0) {
        g_cnt[c] = total;
        g_wself[c] = eself * invZ;
    }
}

// ---------------- 5) weighted sum: grid (2, NCLS), 8 load streams ----------------
__global__ void __launch_bounds__(512) wsum_kernel(const float* __restrict__ x) {
    __shared__ float sred[32];
    __shared__ float sw[MAXA];
    __shared__ int   soff[MAXA];
    int half = blockIdx.x;       // 0..1 (dim halves of 2048)
    int c  = blockIdx.y;
    int tid = threadIdx.x;
    int dim = half * 2048 + tid * 4;
    int total = g_cnt[c];

    for (int i = tid; i < total; i += 512) {
        sw[i] = g_w[c * MAXA + i];
        soff[i] = g_joff[c * MAXA + i];
    }
    __syncthreads();

    float4 ac[8];
#pragma unroll
    for (int s = 0; s < 8; s++) ac[s] = make_float4(0.f, 0.f, 0.f, 0.f);
    int t = 0;
    for (; t + 8 <= total; t += 8) {
#pragma unroll
        for (int s = 0; s < 8; s++) {
            float w = sw[t + s];
            float4 v = __ldg((const float4*)(x + soff[t + s] + dim));
            ac[s].x += w * v.x; ac[s].y += w * v.y; ac[s].z += w * v.z; ac[s].w += w * v.w;
        }
    }
    for (; t < total; t++) {
        float w = sw[t];
        float4 v = __ldg((const float4*)(x + soff[t] + dim));
        ac[0].x += w * v.x; ac[0].y += w * v.y; ac[0].z += w * v.z; ac[0].w += w * v.w;
    }
    float wself = g_wself[c];
    float4 pr = *(const float4*)(g_proto + (size_t)c * D + dim);
    float4 acc;
    acc.x = ((ac[0].x + ac[1].x) + (ac[2].x + ac[3].x)) + ((ac[4].x + ac[5].x) + (ac[6].x + ac[7].x)) + wself * pr.x;
    acc.y = ((ac[0].y + ac[1].y) + (ac[2].y + ac[3].y)) + ((ac[4].y + ac[5].y) + (ac[6].y + ac[7].y)) + wself * pr.y;
    acc.z = ((ac[0].z + ac[1].z) + (ac[2].z + ac[3].z)) + ((ac[4].z + ac[5].z) + (ac[6].z + ac[7].z)) + wself * pr.z;
    acc.w = ((ac[0].w + ac[1].w) + (ac[2].w + ac[3].w)) + ((ac[4].w + ac[5].w) + (ac[6].w + ac[7].w)) + wself * pr.w;
    *(float4*)(g_acc + (size_t)c * D + dim) = acc;
    float ss = acc.x * acc.x + acc.y * acc.y + acc.z * acc.z + acc.w * acc.w;
    float tot = blk_sum(ss, sred);
    if (tid == 0) g_nrmp[c * 2 + half] = tot;
}

// ---------------- 6) normalize + RNA round ----------------
__global__ void __launch_bounds__(1024) norm_kernel() {
    int c = blockIdx.x;
    int i = threadIdx.x;
    float nrm = g_nrmp[c * 2 + 0] + g_nrmp[c * 2 + 1];
    float inv = 1.f / fmaxf(sqrtf(nrm), EPSC);
    float4 a = ((const float4*)(g_acc + (size_t)c * D))[i];
    float4 r;
    r.x = f2tff(a.x * inv); r.y = f2tff(a.y * inv);
    r.z = f2tff(a.z * inv); r.w = f2tff(a.w * inv);
    ((float4*)(g_anh + (size_t)c * D))[i] = r;
}

// ---------------- launch ----------------
extern "C" void kernel_launch(void* const* d_in, const int* in_sizes, int n_in,
                              void* d_out, int out_size) {
    const float* x   = (const float*)d_in[0];
    const float* tao = (const float*)d_in[1];
    float* out = (float*)d_out;

    float *pnh, *anh;
    cudaGetSymbolAddress((void**)&pnh, g_pnh);
    cudaGetSymbolAddress((void**)&anh, g_anh);

    const int smem = NSTG * (BM * APAD + BNROWS * APAD) * 4;   // 97920 B
    const int nblk = (NQ + BM - 1) / BM;                       // 235

    cudaFuncSetAttribute(mma_gemm<0>, cudaFuncAttributeMaxDynamicSharedMemorySize, smem);
    cudaFuncSetAttribute(mma_gemm<1>, cudaFuncAttributeMaxDynamicSharedMemorySize, smem);

    proto_kernel<<<NCLS, 1024>>>(x);
    mma_gemm<0><<<nblk, 128, smem>>>(x, pnh, tao, out);     // out unused in FIN=0
    refine_kernel<<<256, 256>>>(x);
    weights_kernel<<<NCLS, 256>>>();
    wsum_kernel<<<dim3(2, NCLS), 512>>>(x);
    norm_kernel<<<NCLS, 1024>>>();
    mma_gemm<1><<<nblk, 128, smem>>>(x, anh, tao, out);
}

// round 15
// speedup vs baseline: 1.0435x; 1.0435x over previous
#include <cuda_runtime.h>
#include <math.h>

#define D 4096
#define NCLS 100
#define KSUP 5
#define QPER 75
#define ROWSPC 80
#define NQ 7500
#define EPSC 1e-8f
#define GAPT_RAW 0.008f
#define MAXC 8
#define MAXA 1024

// ---------------- scratch ----------------
__device__ float g_proto[NCLS * D];
__device__ float g_pn[NCLS * D];        // exact fp32 normalized protos (refine)
__device__ float g_pnh[NCLS * D];       // RNA tf32 pn (gemm B)
__device__ float g_anh[NCLS * D];       // RNA tf32 adapted protos (gemm B)
__device__ float g_acc[NCLS * D];       // unnormalized adapted protos
__device__ float g_nrmp[NCLS * 2];      // per-half sumsq partials
__device__ float g_self[NCLS];
__device__ float g_qinv[NQ];
__device__ float g_win[NQ];
__device__ int   g_label[NQ];
__device__ int   g_cand[NQ * MAXC];
__device__ int   g_ncand[NQ];
__device__ int   g_work[NQ];
__device__ int   g_nwork;
__device__ float g_w[NCLS * MAXA];
__device__ int   g_joff[NCLS * MAXA];
__device__ int   g_cnt[NCLS];
__device__ float g_wself[NCLS];

__device__ __forceinline__ int qrow(int j) {
    return (j / QPER) * ROWSPC + KSUP + (j % QPER);
}

__device__ __forceinline__ float f2tff(float f) {
    unsigned u;
    asm("cvt.rna.tf32.f32 %0, %1;" : "=r"(u) : "f"(f));
    return __uint_as_float(u);
}

// ---------------- block reductions ----------------
__device__ __forceinline__ float blk_sum(float v, float* sred) {
    int lane = threadIdx.x & 31, w = threadIdx.x >> 5;
#pragma unroll
    for (int o = 16; o > 0; o >>= 1) v += __shfl_down_sync(0xffffffffu, v, o);
    __syncthreads();
    if (lane == 0) sred[w] = v;
    __syncthreads();
    if (w == 0) {
        v = (lane < ((int)blockDim.x >> 5)) ? sred[lane] : 0.f;
#pragma unroll
        for (int o = 16; o > 0; o >>= 1) v += __shfl_down_sync(0xffffffffu, v, o);
        if (lane == 0) sred[0] = v;
    }
    __syncthreads();
    return sred[0];
}

__device__ __forceinline__ float blk_max(float v, float* sred) {
    int lane = threadIdx.x & 31, w = threadIdx.x >> 5;
#pragma unroll
    for (int o = 16; o > 0; o >>= 1) v = fmaxf(v, __shfl_down_sync(0xffffffffu, v, o));
    __syncthreads();
    if (lane == 0) sred[w] = v;
    __syncthreads();
    if (w == 0) {
        v = (lane < ((int)blockDim.x >> 5)) ? sred[lane] : -INFINITY;
#pragma unroll
        for (int o = 16; o > 0; o >>= 1) v = fmaxf(v, __shfl_down_sync(0xffffffffu, v, o));
        if (lane == 0) sred[0] = v;
    }
    __syncthreads();
    return sred[0];
}

// ---------------- 1) prototypes ----------------
__global__ void __launch_bounds__(1024) proto_kernel(const float* __restrict__ x) {
    __shared__ float sred[32];
    int c = blockIdx.x;
    int i = threadIdx.x;
    if (c == 0 && i == 0) g_nwork = 0;
    const float4* sup = (const float4*)(x + (size_t)c * ROWSPC * D);
    const int DQ = D / 4;
    float4 v0 = sup[i];
    float4 v1 = sup[DQ + i];
    float4 v2 = sup[2 * DQ + i];
    float4 v3 = sup[3 * DQ + i];
    float4 v4 = sup[4 * DQ + i];
    float4 s;
    s.x = (v0.x + v1.x + v2.x + v3.x + v4.x) * 0.2f;
    s.y = (v0.y + v1.y + v2.y + v3.y + v4.y) * 0.2f;
    s.z = (v0.z + v1.z + v2.z + v3.z + v4.z) * 0.2f;
    s.w = (v0.w + v1.w + v2.w + v3.w + v4.w) * 0.2f;
    ((float4*)(g_proto + (size_t)c * D))[i] = s;
    float ss = s.x * s.x + s.y * s.y + s.z * s.z + s.w * s.w;
    float tot = blk_sum(ss, sred);
    float inv = 1.f / fmaxf(sqrtf(tot), EPSC);
    float4 p;
    p.x = s.x * inv; p.y = s.y * inv; p.z = s.z * inv; p.w = s.w * inv;
    ((float4*)(g_pn + (size_t)c * D))[i] = p;
    float4 ph;
    ph.x = f2tff(p.x); ph.y = f2tff(p.y); ph.z = f2tff(p.z); ph.w = f2tff(p.w);
    ((float4*)(g_pnh + (size_t)c * D))[i] = ph;
    float ss2 = p.x * p.x + p.y * p.y + p.z * p.z + p.w * p.w;
    float t2 = blk_sum(ss2, sred);
    if (i == 0) g_self[c] = t2;
}

// ---------------- 2)/6) tf32 mma GEMM: BM=64, 256 thr, 4-stage ring, wait_group 2 ----------------
#define BM 64
#define BNROWS 104
#define BK 32
#define APAD 36
#define NSTG 4
#define NIT (D / BK)
#define PSTRIDE 106

#define CPA16(dst, src, sz) \
    asm volatile("cp.async.cg.shared.global [%0], [%1], 16, %2;\n" :: "r"(dst), "l"(src), "r"(sz))

__device__ __forceinline__ void mma_tf32(float c[4], const unsigned a[4], const unsigned b[2]) {
    asm volatile(
        "mma.sync.aligned.m16n8k8.row.col.f32.tf32.tf32.f32 "
        "{%0,%1,%2,%3}, {%4,%5,%6,%7}, {%8,%9}, {%0,%1,%2,%3};\n"
        : "+f"(c[0]), "+f"(c[1]), "+f"(c[2]), "+f"(c[3])
        : "r"(a[0]), "r"(a[1]), "r"(a[2]), "r"(a[3]), "r"(b[0]), "r"(b[1]));
}

template <int FIN>
__global__ void __launch_bounds__(256, 2) mma_gemm(const float* __restrict__ x,
                                                   const float* __restrict__ B,
                                                   const float* __restrict__ taop,
                                                   float* __restrict__ out) {
    extern __shared__ float sm[];
    __shared__ float sq[BM];
    constexpr int SA = BM * APAD;          // 2304
    constexpr int SB = BNROWS * APAD;      // 3744
    constexpr int SS = SA + SB;            // 6048 floats per stage

    const int tid = threadIdx.x;
    const int lane = tid & 31;
    const int warp = tid >> 5;             // 0..7
    const int wM = warp >> 2;              // 0..1
    const int wN = warp & 3;               // 0..3 (wN==3 prunes nt>0)
    const int g = lane >> 2;
    const int t4 = lane & 3;
    const int j0 = blockIdx.x * BM;
    const int nfr = (wN == 3) ? 1 : 4;

    float C[2][4][4];
#pragma unroll
    for (int mt = 0; mt < 2; mt++)
#pragma unroll
        for (int nt = 0; nt < 4; nt++)
#pragma unroll
            for (int r = 0; r < 4; r++) C[mt][nt][r] = 0.f;

    float qq = 0.f;

    const unsigned smbase = (unsigned)__cvta_generic_to_shared(sm);

    auto load_tile = [&](int stg, int k0) {
        unsigned abase = smbase + stg * SS * 4;
#pragma unroll
        for (int i = 0; i < 2; i++) {                  // A: 64 rows * 8 slots = 512
            int idx = tid + i * 256;
            int row = idx >> 3, seg = idx & 7;
            int j = j0 + row;
            const float* src = x + (size_t)qrow(j < NQ ? j : NQ - 1) * D + k0 + seg * 4;
            unsigned dst = abase + (row * APAD + seg * 4) * 4;
            CPA16(dst, src, (j < NQ) ? 16 : 0);
        }
        unsigned bbase = abase + SA * 4;
#pragma unroll
        for (int i = 0; i < 4; i++) {                  // B: 104 rows * 8 slots = 832
            int idx = tid + i * 256;
            if (idx < BNROWS * 8) {
                int n = idx >> 3, seg = idx & 7;
                const float* src = B + (size_t)(n < NCLS ? n : NCLS - 1) * D + k0 + seg * 4;
                unsigned dst = bbase + (n * APAD + seg * 4) * 4;
                CPA16(dst, src, (n < NCLS) ? 16 : 0);
            }
        }
        asm volatile("cp.async.commit_group;\n");
    };

    // prologue: three stages in flight
    load_tile(0, 0);
    load_tile(1, BK);
    load_tile(2, 2 * BK);

    for (int it = 0; it < NIT; it++) {
        int rem = NIT - 1 - it;
        if (rem >= 2)      asm volatile("cp.async.wait_group 2;\n");
        else if (rem == 1) asm volatile("cp.async.wait_group 1;\n");
        else               asm volatile("cp.async.wait_group 0;\n");
        __syncthreads();
        if (it + 3 < NIT) load_tile((it + 3) % NSTG, (it + 3) * BK);

        const float* As = sm + (it % NSTG) * SS;
        const float* Bs = As + SA;

        if (!FIN) {
            const float* Ar = As + (tid >> 2) * APAD + (tid & 3) * 8;
#pragma unroll
            for (int i = 0; i < 8; i++) { float v = Ar[i]; qq += v * v; }
        }

#pragma unroll
        for (int step = 0; step < 4; step++) {
            const int k = step * 8 + t4;
            unsigned a[2][4];
#pragma unroll
            for (int mt = 0; mt < 2; mt++) {
                int r0 = wM * 32 + mt * 16 + g;
                a[mt][0] = __float_as_uint(As[r0 * APAD + k]);
                a[mt][1] = __float_as_uint(As[(r0 + 8) * APAD + k]);
                a[mt][2] = __float_as_uint(As[r0 * APAD + k + 4]);
                a[mt][3] = __float_as_uint(As[(r0 + 8) * APAD + k + 4]);
            }
            unsigned b[4][2];
#pragma unroll
            for (int nt = 0; nt < 4; nt++) {
                if (nt >= nfr) continue;
                int n0 = wN * 32 + nt * 8 + g;
                b[nt][0] = __float_as_uint(Bs[n0 * APAD + k]);
                b[nt][1] = __float_as_uint(Bs[n0 * APAD + k + 4]);
            }
#pragma unroll
            for (int mt = 0; mt < 2; mt++)
#pragma unroll
                for (int nt = 0; nt < 4; nt++) {
                    if (nt >= nfr) continue;
                    mma_tf32(C[mt][nt], a[mt], b[nt]);
                }
        }
        __syncthreads();
    }

    if (!FIN) {
        qq += __shfl_down_sync(0xffffffffu, qq, 1);
        qq += __shfl_down_sync(0xffffffffu, qq, 2);
        if ((tid & 3) == 0) {
            int r = tid >> 2;            // 0..63
            int j = j0 + r;
            float qi = 1.f / fmaxf(sqrtf(qq), EPSC);
            sq[r] = qi;
            if (j < NQ) g_qinv[j] = qi;
        }

        float* pres = sm;
#pragma unroll
        for (int mt = 0; mt < 2; mt++) {
            int r0 = wM * 32 + mt * 16 + g;
#pragma unroll
            for (int half = 0; half < 2; half++) {
                int row = r0 + half * 8;
#pragma unroll
                for (int nt = 0; nt < 4; nt++) {
                    if (nt >= nfr) continue;
                    int c = wN * 32 + nt * 8 + 2 * t4;
                    pres[row * PSTRIDE + c]     = C[mt][nt][half * 2 + 0];
                    pres[row * PSTRIDE + c + 1] = C[mt][nt][half * 2 + 1];
                }
            }
        }
        __syncthreads();

#pragma unroll
        for (int r = 0; r < 8; r++) {
            int row = warp * 8 + r;
            int j = j0 + row;
            if (j >= NQ) continue;
            float v[4];
            float m = -INFINITY;
            int bi = 0x7fffffff;
#pragma unroll
            for (int t = 0; t < 4; t++) {
                int c = lane + 32 * t;
                v[t] = (c < NCLS) ? pres[row * PSTRIDE + c] : -INFINITY;
                if (v[t] > m) { m = v[t]; bi = c; }
            }
#pragma unroll
            for (int o = 16; o > 0; o >>= 1) {
                float ov = __shfl_xor_sync(0xffffffffu, m, o);
                int oi = __shfl_xor_sync(0xffffffffu, bi, o);
                if (ov > m || (ov == m && oi < bi)) { m = ov; bi = oi; }
            }
            float thr = m - GAPT_RAW;
            unsigned lml = (1u << lane) - 1u;
            int base = 0;
#pragma unroll
            for (int t = 0; t < 4; t++) {
                int c = lane + 32 * t;
                bool pred = (c < NCLS) && (v[t] >= thr);
                unsigned mask = __ballot_sync(0xffffffffu, pred);
                if (pred) {
                    int pos = base + __popc(mask & lml);
                    if (pos < MAXC) g_cand[j * MAXC + pos] = c;
                }
                base += __popc(mask);
            }
            if (lane == 0) {
                int nc = min(base, MAXC);
                g_ncand[j] = nc;
                if (nc == 1) {
                    g_label[j] = bi;
                    g_win[j] = m * sq[row];
                } else {
                    int p = atomicAdd(&g_nwork, 1);
                    g_work[p] = j;
                }
            }
        }
    } else {
        const float taov = taop[0];
#pragma unroll
        for (int mt = 0; mt < 2; mt++) {
            int r0 = wM * 32 + mt * 16 + g;
#pragma unroll
            for (int half = 0; half < 2; half++) {
                int j = j0 + r0 + half * 8;
                if (j >= NQ) continue;
                float s = g_qinv[j] * taov;
#pragma unroll
                for (int nt = 0; nt < 4; nt++) {
                    if (nt >= nfr) continue;
                    int c = wN * 32 + nt * 8 + 2 * t4;
                    if (c < NCLS)     out[j * NCLS + c]     = C[mt][nt][half * 2 + 0] * s;
                    if (c + 1 < NCLS) out[j * NCLS + c + 1] = C[mt][nt][half * 2 + 1] * s;
                }
            }
        }
    }
}

// ---------------- 3) exact refine: block per entry, warp per candidate ----------------
__global__ void __launch_bounds__(256) refine_kernel(const float* __restrict__ x) {
    __shared__ float sdot[MAXC];
    int nw = g_nwork;
    int w = threadIdx.x >> 5;
    int lane = threadIdx.x & 31;
    for (int t = blockIdx.x; t < nw; t += gridDim.x) {
        int j = g_work[t];
        int nc = g_ncand[j];
        const float4* q = (const float4*)(x + (size_t)qrow(j) * D);
        if (w < nc) {
            int cc = g_cand[j * MAXC + w];
            const float4* p = (const float4*)(g_pn + (size_t)cc * D);
            float d = 0.f;
#pragma unroll 4
            for (int i = lane; i < D / 4; i += 32) {
                float4 a = q[i], b = p[i];
                d += a.x * b.x + a.y * b.y + a.z * b.z + a.w * b.w;
            }
#pragma unroll
            for (int o = 16; o > 0; o >>= 1) d += __shfl_xor_sync(0xffffffffu, d, o);
            if (lane == 0) sdot[w] = d;
        }
        __syncthreads();
        if (threadIdx.x == 0) {
            float best = -INFINITY;
            int bi = 0x7fffffff;
            for (int i = 0; i < nc; i++) {
                float v = sdot[i];
                int c = g_cand[j * MAXC + i];
                if (v > best || (v == best && c < bi)) { best = v; bi = c; }
            }
            g_label[j] = bi;
            g_win[j] = best * g_qinv[j];
        }
        __syncthreads();
    }
}

// ---------------- 4) softmax weights per class (shfl-scan gather) ----------------
__global__ void __launch_bounds__(256) weights_kernel() {
    __shared__ int   s_off[MAXA];
    __shared__ float sred[32];
    __shared__ int   wtot[9];

    int c = blockIdx.x, tid = threadIdx.x;
    int lane = tid & 31, wrp = tid >> 5;

    const int chunk = (NQ + 255) / 256;     // 30
    int jlo = tid * chunk, jhi = min(NQ, jlo + chunk);
    int cnt = 0;
    for (int j = jlo; j < jhi; j++) cnt += (g_label[j] == c);
    int incl = cnt;
#pragma unroll
    for (int o = 1; o < 32; o <<= 1) {
        int v = __shfl_up_sync(0xffffffffu, incl, o);
        if (lane >= o) incl += v;
    }
    int excl = incl - cnt;
    if (lane == 31) wtot[wrp] = incl;
    __syncthreads();
    if (wrp == 0 && lane < 8) {
        int v = wtot[lane];
        int e = v;
#pragma unroll
        for (int o = 1; o < 8; o <<= 1) {
            int u = __shfl_up_sync(0xffu, e, o);
            if (lane >= o) e += u;
        }
        wtot[lane] = e - v;
        if (lane == 7) wtot[8] = e;
    }
    __syncthreads();
    int pos = wtot[wrp] + excl;
    for (int j = jlo; j < jhi; j++)
        if (g_label[j] == c) { if (pos < MAXA) s_off[pos] = j; pos++; }
    int total = min(wtot[8], MAXA);
    __syncthreads();

    float m = g_self[c];
    for (int t = tid; t < total; t += 256) m = fmaxf(m, g_win[s_off[t]]);
    m = blk_max(m, sred);

    float se = 0.f;
    float ebuf[(MAXA + 255) / 256];
    for (int t = tid, r = 0; t < total; t += 256, r++) {
        float e = expf(g_win[s_off[t]] - m);
        ebuf[r] = e;
        se += e;
    }
    float eself = expf(g_self[c] - m);
    float Z = blk_sum(se, sred) + eself;
    float invZ = 1.f / Z;
    for (int t = tid, r = 0; t < total; t += 256, r++) {
        g_w[c * MAXA + t] = ebuf[r] * invZ;
        g_joff[c * MAXA + t] = qrow(s_off[t]) * D;
    }
    if (tid == 0) {
        g_cnt[c] = total;
        g_wself[c] = eself * invZ;
    }
}

// ---------------- 5) weighted sum: grid (2, NCLS), 8 load streams ----------------
__global__ void __launch_bounds__(512) wsum_kernel(const float* __restrict__ x) {
    __shared__ float sred[32];
    __shared__ float sw[MAXA];
    __shared__ int   soff[MAXA];
    int half = blockIdx.x;
    int c  = blockIdx.y;
    int tid = threadIdx.x;
    int dim = half * 2048 + tid * 4;
    int total = g_cnt[c];

    for (int i = tid; i < total; i += 512) {
        sw[i] = g_w[c * MAXA + i];
        soff[i] = g_joff[c * MAXA + i];
    }
    __syncthreads();

    float4 ac[8];
#pragma unroll
    for (int s = 0; s < 8; s++) ac[s] = make_float4(0.f, 0.f, 0.f, 0.f);
    int t = 0;
    for (; t + 8 <= total; t += 8) {
#pragma unroll
        for (int s = 0; s < 8; s++) {
            float w = sw[t + s];
            float4 v = __ldg((const float4*)(x + soff[t + s] + dim));
            ac[s].x += w * v.x; ac[s].y += w * v.y; ac[s].z += w * v.z; ac[s].w += w * v.w;
        }
    }
    for (; t < total; t++) {
        float w = sw[t];
        float4 v = __ldg((const float4*)(x + soff[t] + dim));
        ac[0].x += w * v.x; ac[0].y += w * v.y; ac[0].z += w * v.z; ac[0].w += w * v.w;
    }
    float wself = g_wself[c];
    float4 pr = *(const float4*)(g_proto + (size_t)c * D + dim);
    float4 acc;
    acc.x = ((ac[0].x + ac[1].x) + (ac[2].x + ac[3].x)) + ((ac[4].x + ac[5].x) + (ac[6].x + ac[7].x)) + wself * pr.x;
    acc.y = ((ac[0].y + ac[1].y) + (ac[2].y + ac[3].y)) + ((ac[4].y + ac[5].y) + (ac[6].y + ac[7].y)) + wself * pr.y;
    acc.z = ((ac[0].z + ac[1].z) + (ac[2].z + ac[3].z)) + ((ac[4].z + ac[5].z) + (ac[6].z + ac[7].z)) + wself * pr.z;
    acc.w = ((ac[0].w + ac[1].w) + (ac[2].w + ac[3].w)) + ((ac[4].w + ac[5].w) + (ac[6].w + ac[7].w)) + wself * pr.w;
    *(float4*)(g_acc + (size_t)c * D + dim) = acc;
    float ss = acc.x * acc.x + acc.y * acc.y + acc.z * acc.z + acc.w * acc.w;
    float tot = blk_sum(ss, sred);
    if (tid == 0) g_nrmp[c * 2 + half] = tot;
}

// ---------------- 6) normalize + RNA round ----------------
__global__ void __launch_bounds__(1024) norm_kernel() {
    int c = blockIdx.x;
    int i = threadIdx.x;
    float nrm = g_nrmp[c * 2 + 0] + g_nrmp[c * 2 + 1];
    float inv = 1.f / fmaxf(sqrtf(nrm), EPSC);
    float4 a = ((const float4*)(g_acc + (size_t)c * D))[i];
    float4 r;
    r.x = f2tff(a.x * inv); r.y = f2tff(a.y * inv);
    r.z = f2tff(a.z * inv); r.w = f2tff(a.w * inv);
    ((float4*)(g_anh + (size_t)c * D))[i] = r;
}

// ---------------- launch ----------------
extern "C" void kernel_launch(void* const* d_in, const int* in_sizes, int n_in,
                              void* d_out, int out_size) {
    const float* x   = (const float*)d_in[0];
    const float* tao = (const float*)d_in[1];
    float* out = (float*)d_out;

    float *pnh, *anh;
    cudaGetSymbolAddress((void**)&pnh, g_pnh);
    cudaGetSymbolAddress((void**)&anh, g_anh);

    const int smem = NSTG * (BM * APAD + BNROWS * APAD) * 4;   // 96768 B
    const int nblk = (NQ + BM - 1) / BM;                       // 118

    cudaFuncSetAttribute(mma_gemm<0>, cudaFuncAttributeMaxDynamicSharedMemorySize, smem);
    cudaFuncSetAttribute(mma_gemm<1>, cudaFuncAttributeMaxDynamicSharedMemorySize, smem);

    proto_kernel<<<NCLS, 1024>>>(x);
    mma_gemm<0><<<nblk, 256, smem>>>(x, pnh, tao, out);     // out unused in FIN=0
    refine_kernel<<<256, 256>>>(x);
    weights_kernel<<<NCLS, 256>>>();
    wsum_kernel<<<dim3(2, NCLS), 512>>>(x);
    norm_kernel<<<NCLS, 1024>>>();
    mma_gemm<1><<<nblk, 256, smem>>>(x, anh, tao, out);
}

// round 16
// speedup vs baseline: 1.0526x; 1.0087x over previous
#include <cuda_runtime.h>
#include <math.h>

#define D 4096
#define NCLS 100
#define KSUP 5
#define QPER 75
#define ROWSPC 80
#define NQ 7500
#define EPSC 1e-8f
#define GAPT_RAW 0.008f
#define MAXC 8
#define MAXA 1024

// ---------------- scratch ----------------
__device__ float g_proto[NCLS * D];
__device__ float g_pn[NCLS * D];        // exact fp32 normalized protos (refine)
__device__ float g_pnh[NCLS * D];       // RNA tf32 pn (gemm B)
__device__ float g_anh[NCLS * D];       // RNA tf32 adapted protos (gemm B)
__device__ float g_acc[NCLS * D];       // unnormalized adapted protos
__device__ float g_nrmp[NCLS * 2];      // per-half sumsq partials
__device__ float g_self[NCLS];
__device__ float g_qinv[NQ];
__device__ float g_win[NQ];
__device__ int   g_label[NQ];
__device__ int   g_cand[NQ * MAXC];
__device__ int   g_ncand[NQ];
__device__ int   g_work[NQ];
__device__ int   g_nwork;

__device__ __forceinline__ int qrow(int j) {
    return (j / QPER) * ROWSPC + KSUP + (j % QPER);
}

__device__ __forceinline__ float f2tff(float f) {
    unsigned u;
    asm("cvt.rna.tf32.f32 %0, %1;" : "=r"(u) : "f"(f));
    return __uint_as_float(u);
}

// ---------------- block reductions ----------------
__device__ __forceinline__ float blk_sum(float v, float* sred) {
    int lane = threadIdx.x & 31, w = threadIdx.x >> 5;
#pragma unroll
    for (int o = 16; o > 0; o >>= 1) v += __shfl_down_sync(0xffffffffu, v, o);
    __syncthreads();
    if (lane == 0) sred[w] = v;
    __syncthreads();
    if (w == 0) {
        v = (lane < ((int)blockDim.x >> 5)) ? sred[lane] : 0.f;
#pragma unroll
        for (int o = 16; o > 0; o >>= 1) v += __shfl_down_sync(0xffffffffu, v, o);
        if (lane == 0) sred[0] = v;
    }
    __syncthreads();
    return sred[0];
}

__device__ __forceinline__ float blk_max(float v, float* sred) {
    int lane = threadIdx.x & 31, w = threadIdx.x >> 5;
#pragma unroll
    for (int o = 16; o > 0; o >>= 1) v = fmaxf(v, __shfl_down_sync(0xffffffffu, v, o));
    __syncthreads();
    if (lane == 0) sred[w] = v;
    __syncthreads();
    if (w == 0) {
        v = (lane < ((int)blockDim.x >> 5)) ? sred[lane] : -INFINITY;
#pragma unroll
        for (int o = 16; o > 0; o >>= 1) v = fmaxf(v, __shfl_down_sync(0xffffffffu, v, o));
        if (lane == 0) sred[0] = v;
    }
    __syncthreads();
    return sred[0];
}

// ---------------- 1) prototypes ----------------
__global__ void __launch_bounds__(1024) proto_kernel(const float* __restrict__ x) {
    __shared__ float sred[32];
    int c = blockIdx.x;
    int i = threadIdx.x;
    if (c == 0 && i == 0) g_nwork = 0;
    const float4* sup = (const float4*)(x + (size_t)c * ROWSPC * D);
    const int DQ = D / 4;
    float4 v0 = sup[i];
    float4 v1 = sup[DQ + i];
    float4 v2 = sup[2 * DQ + i];
    float4 v3 = sup[3 * DQ + i];
    float4 v4 = sup[4 * DQ + i];
    float4 s;
    s.x = (v0.x + v1.x + v2.x + v3.x + v4.x) * 0.2f;
    s.y = (v0.y + v1.y + v2.y + v3.y + v4.y) * 0.2f;
    s.z = (v0.z + v1.z + v2.z + v3.z + v4.z) * 0.2f;
    s.w = (v0.w + v1.w + v2.w + v3.w + v4.w) * 0.2f;
    ((float4*)(g_proto + (size_t)c * D))[i] = s;
    float ss = s.x * s.x + s.y * s.y + s.z * s.z + s.w * s.w;
    float tot = blk_sum(ss, sred);
    float inv = 1.f / fmaxf(sqrtf(tot), EPSC);
    float4 p;
    p.x = s.x * inv; p.y = s.y * inv; p.z = s.z * inv; p.w = s.w * inv;
    ((float4*)(g_pn + (size_t)c * D))[i] = p;
    float4 ph;
    ph.x = f2tff(p.x); ph.y = f2tff(p.y); ph.z = f2tff(p.z); ph.w = f2tff(p.w);
    ((float4*)(g_pnh + (size_t)c * D))[i] = ph;
    float ss2 = p.x * p.x + p.y * p.y + p.z * p.z + p.w * p.w;
    float t2 = blk_sum(ss2, sred);
    if (i == 0) g_self[c] = t2;
}

// ---------------- 2)/5) tf32 mma GEMM: BM=64, 256 thr, 4-stage ring, wait_group 2 ----------------
#define BM 64
#define BNROWS 104
#define BK 32
#define APAD 36
#define NSTG 4
#define NIT (D / BK)
#define PSTRIDE 106

#define CPA16(dst, src, sz) \
    asm volatile("cp.async.cg.shared.global [%0], [%1], 16, %2;\n" :: "r"(dst), "l"(src), "r"(sz))

__device__ __forceinline__ void mma_tf32(float c[4], const unsigned a[4], const unsigned b[2]) {
    asm volatile(
        "mma.sync.aligned.m16n8k8.row.col.f32.tf32.tf32.f32 "
        "{%0,%1,%2,%3}, {%4,%5,%6,%7}, {%8,%9}, {%0,%1,%2,%3};\n"
        : "+f"(c[0]), "+f"(c[1]), "+f"(c[2]), "+f"(c[3])
        : "r"(a[0]), "r"(a[1]), "r"(a[2]), "r"(a[3]), "r"(b[0]), "r"(b[1]));
}

template <int FIN>
__global__ void __launch_bounds__(256, 2) mma_gemm(const float* __restrict__ x,
                                                   const float* __restrict__ B,
                                                   const float* __restrict__ taop,
                                                   float* __restrict__ out) {
    extern __shared__ float sm[];
    __shared__ float sq[BM];
    constexpr int SA = BM * APAD;          // 2304
    constexpr int SB = BNROWS * APAD;      // 3744
    constexpr int SS = SA + SB;            // 6048 floats per stage

    const int tid = threadIdx.x;
    const int lane = tid & 31;
    const int warp = tid >> 5;             // 0..7
    const int wM = warp >> 2;              // 0..1
    const int wN = warp & 3;               // 0..3 (wN==3 prunes nt>0)
    const int g = lane >> 2;
    const int t4 = lane & 3;
    const int j0 = blockIdx.x * BM;
    const int nfr = (wN == 3) ? 1 : 4;

    float C[2][4][4];
#pragma unroll
    for (int mt = 0; mt < 2; mt++)
#pragma unroll
        for (int nt = 0; nt < 4; nt++)
#pragma unroll
            for (int r = 0; r < 4; r++) C[mt][nt][r] = 0.f;

    float qq = 0.f;

    const unsigned smbase = (unsigned)__cvta_generic_to_shared(sm);

    auto load_tile = [&](int stg, int k0) {
        unsigned abase = smbase + stg * SS * 4;
#pragma unroll
        for (int i = 0; i < 2; i++) {                  // A: 64 rows * 8 slots = 512
            int idx = tid + i * 256;
            int row = idx >> 3, seg = idx & 7;
            int j = j0 + row;
            const float* src = x + (size_t)qrow(j < NQ ? j : NQ - 1) * D + k0 + seg * 4;
            unsigned dst = abase + (row * APAD + seg * 4) * 4;
            CPA16(dst, src, (j < NQ) ? 16 : 0);
        }
        unsigned bbase = abase + SA * 4;
#pragma unroll
        for (int i = 0; i < 4; i++) {                  // B: 104 rows * 8 slots = 832
            int idx = tid + i * 256;
            if (idx < BNROWS * 8) {
                int n = idx >> 3, seg = idx & 7;
                const float* src = B + (size_t)(n < NCLS ? n : NCLS - 1) * D + k0 + seg * 4;
                unsigned dst = bbase + (n * APAD + seg * 4) * 4;
                CPA16(dst, src, (n < NCLS) ? 16 : 0);
            }
        }
        asm volatile("cp.async.commit_group;\n");
    };

    // prologue: three stages in flight
    load_tile(0, 0);
    load_tile(1, BK);
    load_tile(2, 2 * BK);

    for (int it = 0; it < NIT; it++) {
        int rem = NIT - 1 - it;
        if (rem >= 2)      asm volatile("cp.async.wait_group 2;\n");
        else if (rem == 1) asm volatile("cp.async.wait_group 1;\n");
        else               asm volatile("cp.async.wait_group 0;\n");
        __syncthreads();
        if (it + 3 < NIT) load_tile((it + 3) % NSTG, (it + 3) * BK);

        const float* As = sm + (it % NSTG) * SS;
        const float* Bs = As + SA;

        if (!FIN) {
            const float* Ar = As + (tid >> 2) * APAD + (tid & 3) * 8;
#pragma unroll
            for (int i = 0; i < 8; i++) { float v = Ar[i]; qq += v * v; }
        }

#pragma unroll
        for (int step = 0; step < 4; step++) {
            const int k = step * 8 + t4;
            unsigned a[2][4];
#pragma unroll
            for (int mt = 0; mt < 2; mt++) {
                int r0 = wM * 32 + mt * 16 + g;
                a[mt][0] = __float_as_uint(As[r0 * APAD + k]);
                a[mt][1] = __float_as_uint(As[(r0 + 8) * APAD + k]);
                a[mt][2] = __float_as_uint(As[r0 * APAD + k + 4]);
                a[mt][3] = __float_as_uint(As[(r0 + 8) * APAD + k + 4]);
            }
            unsigned b[4][2];
#pragma unroll
            for (int nt = 0; nt < 4; nt++) {
                if (nt >= nfr) continue;
                int n0 = wN * 32 + nt * 8 + g;
                b[nt][0] = __float_as_uint(Bs[n0 * APAD + k]);
                b[nt][1] = __float_as_uint(Bs[n0 * APAD + k + 4]);
            }
#pragma unroll
            for (int mt = 0; mt < 2; mt++)
#pragma unroll
                for (int nt = 0; nt < 4; nt++) {
                    if (nt >= nfr) continue;
                    mma_tf32(C[mt][nt], a[mt], b[nt]);
                }
        }
        __syncthreads();
    }

    if (!FIN) {
        qq += __shfl_down_sync(0xffffffffu, qq, 1);
        qq += __shfl_down_sync(0xffffffffu, qq, 2);
        if ((tid & 3) == 0) {
            int r = tid >> 2;            // 0..63
            int j = j0 + r;
            float qi = 1.f / fmaxf(sqrtf(qq), EPSC);
            sq[r] = qi;
            if (j < NQ) g_qinv[j] = qi;
        }

        float* pres = sm;
#pragma unroll
        for (int mt = 0; mt < 2; mt++) {
            int r0 = wM * 32 + mt * 16 + g;
#pragma unroll
            for (int half = 0; half < 2; half++) {
                int row = r0 + half * 8;
#pragma unroll
                for (int nt = 0; nt < 4; nt++) {
                    if (nt >= nfr) continue;
                    int c = wN * 32 + nt * 8 + 2 * t4;
                    pres[row * PSTRIDE + c]     = C[mt][nt][half * 2 + 0];
                    pres[row * PSTRIDE + c + 1] = C[mt][nt][half * 2 + 1];
                }
            }
        }
        __syncthreads();

#pragma unroll
        for (int r = 0; r < 8; r++) {
            int row = warp * 8 + r;
            int j = j0 + row;
            if (j >= NQ) continue;
            float v[4];
            float m = -INFINITY;
            int bi = 0x7fffffff;
#pragma unroll
            for (int t = 0; t < 4; t++) {
                int c = lane + 32 * t;
                v[t] = (c < NCLS) ? pres[row * PSTRIDE + c] : -INFINITY;
                if (v[t] > m) { m = v[t]; bi = c; }
            }
#pragma unroll
            for (int o = 16; o > 0; o >>= 1) {
                float ov = __shfl_xor_sync(0xffffffffu, m, o);
                int oi = __shfl_xor_sync(0xffffffffu, bi, o);
                if (ov > m || (ov == m && oi < bi)) { m = ov; bi = oi; }
            }
            float thr = m - GAPT_RAW;
            unsigned lml = (1u << lane) - 1u;
            int base = 0;
#pragma unroll
            for (int t = 0; t < 4; t++) {
                int c = lane + 32 * t;
                bool pred = (c < NCLS) && (v[t] >= thr);
                unsigned mask = __ballot_sync(0xffffffffu, pred);
                if (pred) {
                    int pos = base + __popc(mask & lml);
                    if (pos < MAXC) g_cand[j * MAXC + pos] = c;
                }
                base += __popc(mask);
            }
            if (lane == 0) {
                int nc = min(base, MAXC);
                g_ncand[j] = nc;
                if (nc == 1) {
                    g_label[j] = bi;
                    g_win[j] = m * sq[row];
                } else {
                    int p = atomicAdd(&g_nwork, 1);
                    g_work[p] = j;
                }
            }
        }
    } else {
        const float taov = taop[0];
#pragma unroll
        for (int mt = 0; mt < 2; mt++) {
            int r0 = wM * 32 + mt * 16 + g;
#pragma unroll
            for (int half = 0; half < 2; half++) {
                int j = j0 + r0 + half * 8;
                if (j >= NQ) continue;
                float s = g_qinv[j] * taov;
#pragma unroll
                for (int nt = 0; nt < 4; nt++) {
                    if (nt >= nfr) continue;
                    int c = wN * 32 + nt * 8 + 2 * t4;
                    if (c < NCLS)     out[j * NCLS + c]     = C[mt][nt][half * 2 + 0] * s;
                    if (c + 1 < NCLS) out[j * NCLS + c + 1] = C[mt][nt][half * 2 + 1] * s;
                }
            }
        }
    }
}

// ---------------- 3) exact refine: block per entry, warp per candidate ----------------
__global__ void __launch_bounds__(256) refine_kernel(const float* __restrict__ x) {
    __shared__ float sdot[MAXC];
    int nw = g_nwork;
    int w = threadIdx.x >> 5;
    int lane = threadIdx.x & 31;
    for (int t = blockIdx.x; t < nw; t += gridDim.x) {
        int j = g_work[t];
        int nc = g_ncand[j];
        const float4* q = (const float4*)(x + (size_t)qrow(j) * D);
        if (w < nc) {
            int cc = g_cand[j * MAXC + w];
            const float4* p = (const float4*)(g_pn + (size_t)cc * D);
            float d = 0.f;
#pragma unroll 4
            for (int i = lane; i < D / 4; i += 32) {
                float4 a = q[i], b = p[i];
                d += a.x * b.x + a.y * b.y + a.z * b.z + a.w * b.w;
            }
#pragma unroll
            for (int o = 16; o > 0; o >>= 1) d += __shfl_xor_sync(0xffffffffu, d, o);
            if (lane == 0) sdot[w] = d;
        }
        __syncthreads();
        if (threadIdx.x == 0) {
            float best = -INFINITY;
            int bi = 0x7fffffff;
            for (int i = 0; i < nc; i++) {
                float v = sdot[i];
                int c = g_cand[j * MAXC + i];
                if (v > best || (v == best && c < bi)) { best = v; bi = c; }
            }
            g_label[j] = bi;
            g_win[j] = best * g_qinv[j];
        }
        __syncthreads();
    }
}

// ---------------- 4) fused gather + softmax + weighted sum: grid (2, NCLS), 512 thr ----------------
__global__ void __launch_bounds__(512) wsum_kernel(const float* __restrict__ x) {
    __shared__ float sred[32];
    __shared__ float sw[MAXA];
    __shared__ int   soff[MAXA];
    __shared__ int   wtot[17];

    int half = blockIdx.x;       // 0..1 (dim halves of 2048)
    int c  = blockIdx.y;
    int tid = threadIdx.x;
    int lane = tid & 31, wrp = tid >> 5;

    // ordered gather via two-level shfl prefix scan (512 threads, 16 warps)
    const int chunk = (NQ + 511) / 512;     // 15
    int jlo = tid * chunk, jhi = min(NQ, jlo + chunk);
    int cnt = 0;
    for (int j = jlo; j < jhi; j++) cnt += (g_label[j] == c);
    int incl = cnt;
#pragma unroll
    for (int o = 1; o < 32; o <<= 1) {
        int v = __shfl_up_sync(0xffffffffu, incl, o);
        if (lane >= o) incl += v;
    }
    int excl = incl - cnt;
    if (lane == 31) wtot[wrp] = incl;
    __syncthreads();
    if (wrp == 0 && lane < 16) {
        int v = wtot[lane];
        int e = v;
#pragma unroll
        for (int o = 1; o < 16; o <<= 1) {
            int u = __shfl_up_sync(0xffffu, e, o);
            if (lane >= o) e += u;
        }
        wtot[lane] = e - v;
        if (lane == 15) wtot[16] = e;
    }
    __syncthreads();
    int pos = wtot[wrp] + excl;
    for (int j = jlo; j < jhi; j++)
        if (g_label[j] == c) { if (pos < MAXA) soff[pos] = j; pos++; }
    int total = min(wtot[16], MAXA);
    __syncthreads();

    // softmax over assigned wins + self (slots tid, tid+512)
    float m = g_self[c];
    for (int t = tid; t < total; t += 512) m = fmaxf(m, g_win[soff[t]]);
    m = blk_max(m, sred);
    float se = 0.f;
    float ebuf[2];
    int nr = 0;
    for (int t = tid; t < total; t += 512, nr++) {
        float e = expf(g_win[soff[t]] - m);
        ebuf[nr] = e;
        se += e;
    }
    float eself = expf(g_self[c] - m);
    float Z = blk_sum(se, sred) + eself;
    float invZ = 1.f / Z;
    float wself = eself * invZ;
    for (int t = tid, r = 0; t < total; t += 512, r++) sw[t] = ebuf[r] * invZ;
    __syncthreads();
    for (int t = tid; t < total; t += 512) soff[t] = qrow(soff[t]) * D;
    __syncthreads();

    // weighted sum over assigned queries, 8 load streams, dims [half*2048 + tid*4]
    int dim = half * 2048 + tid * 4;
    float4 ac[8];
#pragma unroll
    for (int s = 0; s < 8; s++) ac[s] = make_float4(0.f, 0.f, 0.f, 0.f);
    int t = 0;
    for (; t + 8 <= total; t += 8) {
#pragma unroll
        for (int s = 0; s < 8; s++) {
            float w = sw[t + s];
            float4 v = __ldg((const float4*)(x + soff[t + s] + dim));
            ac[s].x += w * v.x; ac[s].y += w * v.y; ac[s].z += w * v.z; ac[s].w += w * v.w;
        }
    }
    for (; t < total; t++) {
        float w = sw[t];
        float4 v = __ldg((const float4*)(x + soff[t] + dim));
        ac[0].x += w * v.x; ac[0].y += w * v.y; ac[0].z += w * v.z; ac[0].w += w * v.w;
    }
    float4 pr = *(const float4*)(g_proto + (size_t)c * D + dim);
    float4 acc;
    acc.x = ((ac[0].x + ac[1].x) + (ac[2].x + ac[3].x)) + ((ac[4].x + ac[5].x) + (ac[6].x + ac[7].x)) + wself * pr.x;
    acc.y = ((ac[0].y + ac[1].y) + (ac[2].y + ac[3].y)) + ((ac[4].y + ac[5].y) + (ac[6].y + ac[7].y)) + wself * pr.y;
    acc.z = ((ac[0].z + ac[1].z) + (ac[2].z + ac[3].z)) + ((ac[4].z + ac[5].z) + (ac[6].z + ac[7].z)) + wself * pr.z;
    acc.w = ((ac[0].w + ac[1].w) + (ac[2].w + ac[3].w)) + ((ac[4].w + ac[5].w) + (ac[6].w + ac[7].w)) + wself * pr.w;
    *(float4*)(g_acc + (size_t)c * D + dim) = acc;
    float ss = acc.x * acc.x + acc.y * acc.y + acc.z * acc.z + acc.w * acc.w;
    float tot = blk_sum(ss, sred);
    if (tid == 0) g_nrmp[c * 2 + half] = tot;
}

// ---------------- 5) normalize + RNA round ----------------
__global__ void __launch_bounds__(1024) norm_kernel() {
    int c = blockIdx.x;
    int i = threadIdx.x;
    float nrm = g_nrmp[c * 2 + 0] + g_nrmp[c * 2 + 1];
    float inv = 1.f / fmaxf(sqrtf(nrm), EPSC);
    float4 a = ((const float4*)(g_acc + (size_t)c * D))[i];
    float4 r;
    r.x = f2tff(a.x * inv); r.y = f2tff(a.y * inv);
    r.z = f2tff(a.z * inv); r.w = f2tff(a.w * inv);
    ((float4*)(g_anh + (size_t)c * D))[i] = r;
}

// ---------------- launch ----------------
extern "C" void kernel_launch(void* const* d_in, const int* in_sizes, int n_in,
                              void* d_out, int out_size) {
    const float* x   = (const float*)d_in[0];
    const float* tao = (const float*)d_in[1];
    float* out = (float*)d_out;

    float *pnh, *anh;
    cudaGetSymbolAddress((void**)&pnh, g_pnh);
    cudaGetSymbolAddress((void**)&anh, g_anh);

    const int smem = NSTG * (BM * APAD + BNROWS * APAD) * 4;   // 96768 B
    const int nblk = (NQ + BM - 1) / BM;                       // 118

    cudaFuncSetAttribute(mma_gemm<0>, cudaFuncAttributeMaxDynamicSharedMemorySize, smem);
    cudaFuncSetAttribute(mma_gemm<1>, cudaFuncAttributeMaxDynamicSharedMemorySize, smem);

    proto_kernel<<<NCLS, 1024>>>(x);
    mma_gemm<0><<<nblk, 256, smem>>>(x, pnh, tao, out);     // out unused in FIN=0
    refine_kernel<<<256, 256>>>(x);
    wsum_kernel<<<dim3(2, NCLS), 512>>>(x);
    norm_kernel<<<NCLS, 1024>>>();
    mma_gemm<1><<<nblk, 256, smem>>>(x, anh, tao, out);
}